// round 7
// baseline (speedup 1.0000x reference)
#include <cuda_runtime.h>

// IF spiking neuron forward:
//   mem0 = dtmem * thresh
//   for t: mem += x_t; spike = (mem >= thresh) ? thresh : 0; mem -= spike
//
// Mapping: one thread per (batch, feature-vec4) site; T loop in registers.
// grid.x = B (fast launch dim -> blocks sharing a feature chunk's params
// launch adjacently, so thresh/dtmem reads after the first are L2-served).
// All 4 loads front-batched (read burst), all 4 spikes computed into regs,
// then all 4 stores issued back-to-back (write burst) -- groups DRAM
// read/write phases to cut bus-turnaround overhead on the 50/50 mix.
// Default cache policy (.cs measured ~6% BW penalty on sm_103a, R2-R4).

#define T_STEPS 4

__global__ __launch_bounds__(256, 6) void if_fwd_kernel(
    const float4* __restrict__ x,      // [T, B, feat_v]
    const float4* __restrict__ thresh, // [feat_v]
    const float4* __restrict__ dtmem,  // [feat_v]
    float4* __restrict__ out,          // [T, B, feat_v]
    int feat_v,                        // 1024*3072/4
    int n_per_t_v)                     // B*feat_v (t-stride in vec4)
{
    int f = blockIdx.y * blockDim.x + threadIdx.x;
    if (f >= feat_v) return;

    int b = blockIdx.x;
    long long base = (long long)b * feat_v + f;

    // Read burst: 4 independent time-step loads + params (MLP=6).
    float4 xv0 = __ldg(&x[base]);
    float4 xv1 = __ldg(&x[base + (long long)n_per_t_v]);
    float4 xv2 = __ldg(&x[base + 2LL * n_per_t_v]);
    float4 xv3 = __ldg(&x[base + 3LL * n_per_t_v]);

    float4 th = __ldg(&thresh[f]);
    float4 dm = __ldg(&dtmem[f]);

    float4 mem;
    mem.x = dm.x * th.x;
    mem.y = dm.y * th.y;
    mem.z = dm.z * th.z;
    mem.w = dm.w * th.w;

    float4 s0, s1, s2, s3;

#define STEP(xv, sp)                                                        \
    mem.x += xv.x; sp.x = (mem.x >= th.x) ? th.x : 0.0f; mem.x -= sp.x;     \
    mem.y += xv.y; sp.y = (mem.y >= th.y) ? th.y : 0.0f; mem.y -= sp.y;     \
    mem.z += xv.z; sp.z = (mem.z >= th.z) ? th.z : 0.0f; mem.z -= sp.z;     \
    mem.w += xv.w; sp.w = (mem.w >= th.w) ? th.w : 0.0f; mem.w -= sp.w;

    STEP(xv0, s0)
    STEP(xv1, s1)
    STEP(xv2, s2)
    STEP(xv3, s3)
#undef STEP

    // Write burst: 4 STG.128 back-to-back.
    out[base]                        = s0;
    out[base + (long long)n_per_t_v] = s1;
    out[base + 2LL * n_per_t_v]      = s2;
    out[base + 3LL * n_per_t_v]      = s3;
}

extern "C" void kernel_launch(void* const* d_in, const int* in_sizes, int n_in,
                              void* d_out, int out_size) {
    const float* x      = (const float*)d_in[0];
    const float* thresh = (const float*)d_in[1];
    const float* dtmem  = (const float*)d_in[2];
    float* out          = (float*)d_out;

    int total  = in_sizes[0];           // T*B*1024*3072
    int feat_n = in_sizes[1];           // 1024*3072
    int B      = total / (T_STEPS * feat_n);

    int feat_v    = feat_n / 4;
    int n_per_t_v = B * feat_v;

    int threads = 256;
    dim3 grid(B, (feat_v + threads - 1) / threads);

    if_fwd_kernel<<<grid, threads>>>(
        (const float4*)x, (const float4*)thresh, (const float4*)dtmem,
        (float4*)out, feat_v, n_per_t_v);
}

// round 8
// speedup vs baseline: 1.0008x; 1.0008x over previous
#include <cuda_runtime.h>

// IF spiking neuron forward:
//   mem0 = dtmem * thresh
//   for t: mem += x_t; spike = (mem >= thresh) ? thresh : 0; mem -= spike
//
// Final structure (R5/R7 family, pinned at the sm_103a LTS throughput cap):
//  - one thread per (batch, feature-vec4) site; T loop fully in registers
//  - grid.x = B (fast launch dim): the 8 blocks sharing a feature chunk's
//    thresh/dtmem launch adjacently -> param reads L2-served (traffic at
//    the ~780MB floor: x once, out once, params ~once)
//  - read burst (4 x-loads + 2 param loads front-batched, MLP=6), then all
//    spikes computed, then 4 STG.128 write burst
//  - default cache policy (.cs hints measured ~6% BW penalty in R2-R4)
//  - 512-thread blocks: tighter param L2 locality, fewer wave transitions

#define T_STEPS 4

__global__ __launch_bounds__(512) void if_fwd_kernel(
    const float4* __restrict__ x,      // [T, B, feat_v]
    const float4* __restrict__ thresh, // [feat_v]
    const float4* __restrict__ dtmem,  // [feat_v]
    float4* __restrict__ out,          // [T, B, feat_v]
    int feat_v,                        // 1024*3072/4
    int n_per_t_v)                     // B*feat_v (t-stride in vec4)
{
    int f = blockIdx.y * blockDim.x + threadIdx.x;
    if (f >= feat_v) return;

    int b = blockIdx.x;
    long long base = (long long)b * feat_v + f;

    // Read burst: 4 independent time-step loads + params.
    float4 xv0 = __ldg(&x[base]);
    float4 xv1 = __ldg(&x[base + (long long)n_per_t_v]);
    float4 xv2 = __ldg(&x[base + 2LL * n_per_t_v]);
    float4 xv3 = __ldg(&x[base + 3LL * n_per_t_v]);

    float4 th = __ldg(&thresh[f]);
    float4 dm = __ldg(&dtmem[f]);

    float4 mem;
    mem.x = dm.x * th.x;
    mem.y = dm.y * th.y;
    mem.z = dm.z * th.z;
    mem.w = dm.w * th.w;

    float4 s0, s1, s2, s3;

#define STEP(xv, sp)                                                        \
    mem.x += xv.x; sp.x = (mem.x >= th.x) ? th.x : 0.0f; mem.x -= sp.x;     \
    mem.y += xv.y; sp.y = (mem.y >= th.y) ? th.y : 0.0f; mem.y -= sp.y;     \
    mem.z += xv.z; sp.z = (mem.z >= th.z) ? th.z : 0.0f; mem.z -= sp.z;     \
    mem.w += xv.w; sp.w = (mem.w >= th.w) ? th.w : 0.0f; mem.w -= sp.w;

    STEP(xv0, s0)
    STEP(xv1, s1)
    STEP(xv2, s2)
    STEP(xv3, s3)
#undef STEP

    // Write burst: 4 STG.128 back-to-back.
    out[base]                        = s0;
    out[base + (long long)n_per_t_v] = s1;
    out[base + 2LL * n_per_t_v]      = s2;
    out[base + 3LL * n_per_t_v]      = s3;
}

extern "C" void kernel_launch(void* const* d_in, const int* in_sizes, int n_in,
                              void* d_out, int out_size) {
    const float* x      = (const float*)d_in[0];
    const float* thresh = (const float*)d_in[1];
    const float* dtmem  = (const float*)d_in[2];
    float* out          = (float*)d_out;

    int total  = in_sizes[0];           // T*B*1024*3072
    int feat_n = in_sizes[1];           // 1024*3072
    int B      = total / (T_STEPS * feat_n);

    int feat_v    = feat_n / 4;
    int n_per_t_v = B * feat_v;

    int threads = 512;
    dim3 grid(B, (feat_v + threads - 1) / threads);

    if_fwd_kernel<<<grid, threads>>>(
        (const float4*)x, (const float4*)thresh, (const float4*)dtmem,
        (float4*)out, feat_v, n_per_t_v);
}